// round 1
// baseline (speedup 1.0000x reference)
#include <cuda_runtime.h>
#include <math.h>

#define BB 16
#define T2 2048
#define T1 512
#define FD 128
#define WIN 3.0f
#define DELTA 10.0f
#define EPS 1e-8f

// ------------- scratch (device globals; no runtime allocation) -------------
__device__ double g_prop[BB * T2];   // imv_proposal, fp64
__device__ float  g_act [BB * T2];   // activity * am
__device__ float  g_Z   [BB * T2];   // softmax denominator per frame
__device__ int    g_nvalid[BB];      // valid frame count per batch

// ------------- kernel 1: imv_proposal = alpha[b,t,:] . arange(T1) ---------
__global__ void prop_kernel(const float* __restrict__ alpha) {
    int warp = (blockIdx.x * blockDim.x + threadIdx.x) >> 5;
    int lane = threadIdx.x & 31;
    if (warp >= BB * T2) return;
    const float4* row = (const float4*)(alpha + (size_t)warp * T1);
    double acc = 0.0;
#pragma unroll
    for (int i = 0; i < 4; i++) {
        int idx = lane + i * 32;          // float4 index within row (0..127)
        float4 v = row[idx];
        int s = idx * 4;
        acc += (double)v.x * s + (double)v.y * (s + 1)
             + (double)v.z * (s + 2) + (double)v.w * (s + 3);
    }
#pragma unroll
    for (int o = 16; o; o >>= 1) acc += __shfl_down_sync(0xffffffffu, acc, o);
    if (lane == 0) g_prop[warp] = acc;
}

// ------------- kernel 2: activity from consecutive-frame cosine sim -------
__global__ void act_kernel(const float* __restrict__ mels,
                           const int* __restrict__ mel_mask) {
    int warp = (blockIdx.x * blockDim.x + threadIdx.x) >> 5;
    int lane = threadIdx.x & 31;
    if (warp >= BB * T2) return;
    int t = warp & (T2 - 1);
    float am = (mel_mask[warp] != 0) ? 1.0f : 0.0f;
    if (t == 0) { if (lane == 0) g_act[warp] = am; return; }
    const float4* r0 = (const float4*)(mels + (size_t)(warp - 1) * FD);
    const float4* r1 = (const float4*)(mels + (size_t)warp * FD);
    float4 a = r0[lane], b = r1[lane];
    float dot = a.x * b.x + a.y * b.y + a.z * b.z + a.w * b.w;
    float na  = a.x * a.x + a.y * a.y + a.z * a.z + a.w * a.w;
    float nb  = b.x * b.x + b.y * b.y + b.z * b.z + b.w * b.w;
#pragma unroll
    for (int o = 16; o; o >>= 1) {
        dot += __shfl_down_sync(0xffffffffu, dot, o);
        na  += __shfl_down_sync(0xffffffffu, na,  o);
        nb  += __shfl_down_sync(0xffffffffu, nb,  o);
    }
    if (lane == 0) {
        float n0 = fmaxf(sqrtf(na), 1e-12f);
        float n1 = fmaxf(sqrtf(nb), 1e-12f);
        float cs = dot / (n0 * n1);
        float act = 1.0f / (1.0f + expf(-10.0f * (0.9f - cs)));
        g_act[warp] = act * am;
    }
}

// ------------- kernel 3: per-batch gated cumsum + rescale -> imv ----------
__global__ void scan_kernel(const int* __restrict__ mel_mask,
                            const int* __restrict__ text_mask,
                            float* __restrict__ imv_out) {
    int b = blockIdx.x;
    int tid = threadIdx.x;                 // 256 threads, 8 elems each
    __shared__ float s_cum[T2];
    __shared__ float s_part[256];
    __shared__ int   s_red[256];
    __shared__ float s_scale;

    float vals[8];
    float run = 0.0f;
    int nv_local = 0;
#pragma unroll
    for (int i = 0; i < 8; i++) {
        int t = tid * 8 + i;
        int gi = b * T2 + t;
        float eff = 0.0f;
        if (t > 0) {
            double d = g_prop[gi] - g_prop[gi - 1];
            float e = (float)d * g_act[gi];
            eff = fminf(fmaxf(e, 0.0f), 1.0f);
        }
        run += eff;
        vals[i] = run;
        nv_local += (mel_mask[gi] != 0);
    }
    s_part[tid] = run;
    s_red[tid]  = nv_local;
    __syncthreads();
    // inclusive Hillis-Steele scan of 256 partials (read, sync, write, sync)
    for (int off = 1; off < 256; off <<= 1) {
        float v = (tid >= off) ? s_part[tid - off] : 0.0f;
        __syncthreads();
        s_part[tid] += v;
        __syncthreads();
    }
    float offset = (tid > 0) ? s_part[tid - 1] : 0.0f;
#pragma unroll
    for (int i = 0; i < 8; i++) s_cum[tid * 8 + i] = vals[i] + offset;

    // reductions: nvalid over mel_mask, text_len over text_mask
    for (int off = 128; off; off >>= 1) {
        __syncthreads();
        if (tid < off) s_red[tid] += s_red[tid + off];
    }
    __syncthreads();
    int nvalid = s_red[0];
    __syncthreads();
    int tl = (text_mask[b * T1 + tid] != 0) + (text_mask[b * T1 + 256 + tid] != 0);
    s_red[tid] = tl;
    for (int off = 128; off; off >>= 1) {
        __syncthreads();
        if (tid < off) s_red[tid] += s_red[tid + off];
    }
    __syncthreads();
    if (tid == 0) {
        int text_len = s_red[0];
        int last_idx = max(nvalid - 1, 0);
        float aml = (mel_mask[b * T2 + last_idx] != 0) ? 1.0f : 0.0f;
        float last_val = fmaxf(s_cum[last_idx] * aml, 1e-6f);
        float scale = fmaxf((float)text_len - 1.0f, 0.0f) / last_val;
        s_scale = scale;
        g_nvalid[b] = nvalid;
    }
    __syncthreads();
    float scale = s_scale;
#pragma unroll
    for (int i = 0; i < 8; i++) {
        int t = tid * 8 + i;
        int gi = b * T2 + t;
        float am = (mel_mask[gi] != 0) ? 1.0f : 0.0f;
        imv_out[gi] = s_cum[t] * am * scale;
    }
}

// ------------- kernel 4: windowed softmax denominator Z[b,t] --------------
__global__ void zed_kernel(const float* __restrict__ imv,
                           const int* __restrict__ text_mask) {
    int gi = blockIdx.x * blockDim.x + threadIdx.x;
    if (gi >= BB * T2) return;
    int b = gi / T2;
    float v = imv[gi];
    int s0 = max(0, (int)ceilf(v - WIN));
    int s1 = min(T1 - 1, (int)floorf(v + WIN));
    float Z = 0.0f;
    for (int s = s0; s <= s1; s++) {
        if (text_mask[b * T1 + s]) {
            float d = v - (float)s;
            Z += expf(-DELTA * d * d);
        }
    }
    g_Z[gi] = Z;
}

// ------------- kernel 5: gather aligned_mels + durations ------------------
__global__ void align_kernel(const float* __restrict__ mels,
                             const int* __restrict__ mel_mask,
                             const int* __restrict__ text_mask,
                             const float* __restrict__ imv,
                             float* __restrict__ aligned,
                             float* __restrict__ durations) {
    int s = blockIdx.x;
    int b = blockIdx.y;
    int f = threadIdx.x;                      // 128 threads == FD
    __shared__ int s_range[2];

    int tm = text_mask[b * T1 + s];
    const float* imvb = imv + b * T2;
    if (f == 0) {
        int n = g_nvalid[b];
        float lo = (float)s - WIN, hi = (float)s + WIN;
        int a = 0, c = n;
        while (a < c) { int m = (a + c) >> 1; if (imvb[m] < lo) a = m + 1; else c = m; }
        s_range[0] = a;
        int a2 = a, c2 = n;
        while (a2 < c2) { int m = (a2 + c2) >> 1; if (imvb[m] <= hi) a2 = m + 1; else c2 = m; }
        s_range[1] = a2;
    }
    __syncthreads();

    float acc = 0.0f, D = 0.0f;
    if (tm) {
        int t0 = s_range[0], t1 = s_range[1];
        for (int t = t0; t < t1; t++) {
            int gi = b * T2 + t;
            if (!mel_mask[gi]) continue;
            float v = imvb[t];
            float Z = g_Z[gi];
            float d = v - (float)s;
            float e = expf(-DELTA * d * d);
            float g = (Z > 0.0f) ? (e / Z) : 0.0f;
            acc += g * mels[(size_t)gi * FD + f];
            D   += g;
        }
    }
    aligned[((size_t)(b * T1 + s)) * FD + f] = tm ? (acc / (D + EPS)) : 0.0f;
    if (f == 0) durations[b * T1 + s] = tm ? D : 0.0f;
}

// ------------- launch ------------------------------------------------------
extern "C" void kernel_launch(void* const* d_in, const int* in_sizes, int n_in,
                              void* d_out, int out_size) {
    const float* mels      = (const float*)d_in[0];  // [B,T2,F]
    const float* alpha     = (const float*)d_in[1];  // [B,T2,T1]
    const int*   mel_mask  = (const int*)d_in[2];    // [B,T2]
    const int*   text_mask = (const int*)d_in[3];    // [B,T1]

    float* out       = (float*)d_out;
    float* aligned   = out;                              // B*T1*F
    float* durations = out + (size_t)BB * T1 * FD;       // B*T1
    float* imv       = durations + (size_t)BB * T1;      // B*T2

    int nwarp = BB * T2;
    int nblk  = (nwarp * 32 + 255) / 256;

    prop_kernel<<<nblk, 256>>>(alpha);
    act_kernel<<<nblk, 256>>>(mels, mel_mask);
    scan_kernel<<<BB, 256>>>(mel_mask, text_mask, imv);
    zed_kernel<<<(BB * T2 + 255) / 256, 256>>>(imv, text_mask);
    dim3 grid(T1, BB);
    align_kernel<<<grid, FD>>>(mels, mel_mask, text_mask, imv, aligned, durations);
}

// round 3
// speedup vs baseline: 4.0819x; 4.0819x over previous
#include <cuda_runtime.h>
#include <math.h>

#define BB 16
#define T2 2048
#define T1 512
#define FD 128
#define WIN 3.0f
#define DELTA 10.0f
#define EPS 1e-8f

// ------------- scratch (device globals; no runtime allocation) -------------
__device__ double g_prop[BB * T2];   // imv_proposal, fp64 accumulated
__device__ float  g_act [BB * T2];   // activity * am
__device__ float  g_Z   [BB * T2];   // softmax denominator per frame
__device__ int    g_nvalid[BB];      // valid frame count per batch

// ------------- kernel 1: imv_proposal = alpha[b,t,:] . arange(T1) ---------
// fp32 dot within each float4 (|partial| <= 2044, err ~2e-4 abs), fp64 sum.
__global__ void prop_kernel(const float* __restrict__ alpha) {
    int warp = (blockIdx.x * blockDim.x + threadIdx.x) >> 5;
    int lane = threadIdx.x & 31;
    if (warp >= BB * T2) return;
    const float4* row = (const float4*)(alpha + (size_t)warp * T1);
    double acc = 0.0;
#pragma unroll
    for (int i = 0; i < 4; i++) {
        int idx = lane + i * 32;          // float4 index within row (0..127)
        float4 v = row[idx];
        float s = (float)(idx * 4);
        float p = v.x * s + v.y * (s + 1.0f) + v.z * (s + 2.0f) + v.w * (s + 3.0f);
        acc += (double)p;
    }
#pragma unroll
    for (int o = 16; o; o >>= 1) acc += __shfl_down_sync(0xffffffffu, acc, o);
    if (lane == 0) g_prop[warp] = acc;
}

// ------------- kernel 2: activity from consecutive-frame cosine sim -------
__global__ void act_kernel(const float* __restrict__ mels,
                           const int* __restrict__ mel_mask) {
    int warp = (blockIdx.x * blockDim.x + threadIdx.x) >> 5;
    int lane = threadIdx.x & 31;
    if (warp >= BB * T2) return;
    int t = warp & (T2 - 1);
    float am = (mel_mask[warp] != 0) ? 1.0f : 0.0f;
    if (t == 0) { if (lane == 0) g_act[warp] = am; return; }
    const float4* r0 = (const float4*)(mels + (size_t)(warp - 1) * FD);
    const float4* r1 = (const float4*)(mels + (size_t)warp * FD);
    float4 a = r0[lane], b = r1[lane];
    float dot = a.x * b.x + a.y * b.y + a.z * b.z + a.w * b.w;
    float na  = a.x * a.x + a.y * a.y + a.z * a.z + a.w * a.w;
    float nb  = b.x * b.x + b.y * b.y + b.z * b.z + b.w * b.w;
#pragma unroll
    for (int o = 16; o; o >>= 1) {
        dot += __shfl_down_sync(0xffffffffu, dot, o);
        na  += __shfl_down_sync(0xffffffffu, na,  o);
        nb  += __shfl_down_sync(0xffffffffu, nb,  o);
    }
    if (lane == 0) {
        float n0 = fmaxf(sqrtf(na), 1e-12f);
        float n1 = fmaxf(sqrtf(nb), 1e-12f);
        float cs = dot / (n0 * n1);
        float act = 1.0f / (1.0f + expf(-10.0f * (0.9f - cs)));
        g_act[warp] = act * am;
    }
}

// ------------- kernel 3: per-batch gated cumsum + rescale -> imv ----------
__global__ void scan_kernel(const int* __restrict__ mel_mask,
                            const int* __restrict__ text_mask,
                            float* __restrict__ imv_out) {
    int b = blockIdx.x;
    int tid = threadIdx.x;                 // 256 threads, 8 elems each
    __shared__ float s_cum[T2];
    __shared__ float s_part[256];
    __shared__ int   s_red[256];
    __shared__ float s_scale;

    float vals[8];
    float run = 0.0f;
    int nv_local = 0;
#pragma unroll
    for (int i = 0; i < 8; i++) {
        int t = tid * 8 + i;
        int gi = b * T2 + t;
        float eff = 0.0f;
        if (t > 0) {
            double d = g_prop[gi] - g_prop[gi - 1];
            float e = (float)d * g_act[gi];
            eff = fminf(fmaxf(e, 0.0f), 1.0f);
        }
        run += eff;
        vals[i] = run;
        nv_local += (mel_mask[gi] != 0);
    }
    s_part[tid] = run;
    s_red[tid]  = nv_local;
    __syncthreads();
    for (int off = 1; off < 256; off <<= 1) {
        float v = (tid >= off) ? s_part[tid - off] : 0.0f;
        __syncthreads();
        s_part[tid] += v;
        __syncthreads();
    }
    float offset = (tid > 0) ? s_part[tid - 1] : 0.0f;
#pragma unroll
    for (int i = 0; i < 8; i++) s_cum[tid * 8 + i] = vals[i] + offset;

    for (int off = 128; off; off >>= 1) {
        __syncthreads();
        if (tid < off) s_red[tid] += s_red[tid + off];
    }
    __syncthreads();
    int nvalid = s_red[0];
    __syncthreads();
    int tl = (text_mask[b * T1 + tid] != 0) + (text_mask[b * T1 + 256 + tid] != 0);
    s_red[tid] = tl;
    for (int off = 128; off; off >>= 1) {
        __syncthreads();
        if (tid < off) s_red[tid] += s_red[tid + off];
    }
    __syncthreads();
    if (tid == 0) {
        int text_len = s_red[0];
        int last_idx = max(nvalid - 1, 0);
        float aml = (mel_mask[b * T2 + last_idx] != 0) ? 1.0f : 0.0f;
        float last_val = fmaxf(s_cum[last_idx] * aml, 1e-6f);
        float scale = fmaxf((float)text_len - 1.0f, 0.0f) / last_val;
        s_scale = scale;
        g_nvalid[b] = nvalid;
    }
    __syncthreads();
    float scale = s_scale;
#pragma unroll
    for (int i = 0; i < 8; i++) {
        int t = tid * 8 + i;
        int gi = b * T2 + t;
        float am = (mel_mask[gi] != 0) ? 1.0f : 0.0f;
        imv_out[gi] = s_cum[t] * am * scale;
    }
}

// ------------- kernel 4: windowed softmax denominator Z[b,t] --------------
__global__ void zed_kernel(const float* __restrict__ imv,
                           const int* __restrict__ text_mask) {
    int gi = blockIdx.x * blockDim.x + threadIdx.x;
    if (gi >= BB * T2) return;
    int b = gi / T2;
    float v = imv[gi];
    int s0 = max(0, (int)ceilf(v - WIN));
    int s1 = min(T1 - 1, (int)floorf(v + WIN));
    float Z = 0.0f;
    for (int s = s0; s <= s1; s++) {
        if (text_mask[b * T1 + s]) {
            float d = v - (float)s;
            Z += expf(-DELTA * d * d);
        }
    }
    g_Z[gi] = Z;
}

// ------------- kernel 5: gather aligned_mels + durations ------------------
// Weights computed ONCE per (b,s,t) into shared; F-threads only do FMA+LDG.
__global__ void align_kernel(const float* __restrict__ mels,
                             const int* __restrict__ mel_mask,
                             const int* __restrict__ text_mask,
                             const float* __restrict__ imv,
                             float* __restrict__ aligned,
                             float* __restrict__ durations) {
    int s = blockIdx.x;
    int b = blockIdx.y;
    int f = threadIdx.x;                      // 128 threads == FD
    __shared__ int s_range[2];
    __shared__ float s_w[FD];

    int tm = text_mask[b * T1 + s];
    const float* imvb = imv + b * T2;
    if (f == 0) {
        int n = g_nvalid[b];
        float lo = (float)s - WIN, hi = (float)s + WIN;
        int a = 0, c = n;
        while (a < c) { int m = (a + c) >> 1; if (imvb[m] < lo) a = m + 1; else c = m; }
        s_range[0] = a;
        int a2 = a, c2 = n;
        while (a2 < c2) { int m = (a2 + c2) >> 1; if (imvb[m] <= hi) a2 = m + 1; else c2 = m; }
        s_range[1] = a2;
    }
    __syncthreads();

    float acc = 0.0f, D = 0.0f;
    int t0 = s_range[0], t1 = s_range[1];
    if (tm) {
        for (int base = t0; base < t1; base += FD) {
            int nt = min(FD, t1 - base);
            __syncthreads();
            if (f < nt) {
                int gi = b * T2 + base + f;
                float w = 0.0f;
                if (mel_mask[gi]) {
                    float v = imvb[base + f];
                    float Z = g_Z[gi];
                    float d = v - (float)s;
                    float e = expf(-DELTA * d * d);
                    w = (Z > 0.0f) ? (e / Z) : 0.0f;
                }
                s_w[f] = w;
            }
            __syncthreads();
            const float* mb = mels + ((size_t)(b * T2 + base)) * FD + f;
            for (int j = 0; j < nt; j++) {
                float w = s_w[j];
                acc += w * mb[(size_t)j * FD];
                D   += w;
            }
        }
    }
    aligned[((size_t)(b * T1 + s)) * FD + f] = tm ? (acc / (D + EPS)) : 0.0f;
    if (f == 0) durations[b * T1 + s] = tm ? D : 0.0f;
}

// ------------- launch ------------------------------------------------------
extern "C" void kernel_launch(void* const* d_in, const int* in_sizes, int n_in,
                              void* d_out, int out_size) {
    const float* mels      = (const float*)d_in[0];  // [B,T2,F]
    const float* alpha     = (const float*)d_in[1];  // [B,T2,T1]
    const int*   mel_mask  = (const int*)d_in[2];    // [B,T2]
    const int*   text_mask = (const int*)d_in[3];    // [B,T1]

    float* out       = (float*)d_out;
    float* aligned   = out;                              // B*T1*F
    float* durations = out + (size_t)BB * T1 * FD;       // B*T1
    float* imv       = durations + (size_t)BB * T1;      // B*T2

    int nwarp = BB * T2;
    int nblk  = (nwarp * 32 + 255) / 256;

    prop_kernel<<<nblk, 256>>>(alpha);
    act_kernel<<<nblk, 256>>>(mels, mel_mask);
    scan_kernel<<<BB, 256>>>(mel_mask, text_mask, imv);
    zed_kernel<<<(BB * T2 + 255) / 256, 256>>>(imv, text_mask);
    dim3 grid(T1, BB);
    align_kernel<<<grid, FD>>>(mels, mel_mask, text_mask, imv, aligned, durations);
}

// round 4
// speedup vs baseline: 4.4902x; 1.1000x over previous
#include <cuda_runtime.h>
#include <math.h>

#define BB 16
#define T2 2048
#define T1 512
#define FD 128
#define WIN 3.0f
#define DELTA 10.0f
#define EPS 1e-8f

// ------------- scratch (device globals; no runtime allocation) -------------
__device__ double g_prop[BB * T2];   // imv_proposal, fp64 accumulated
__device__ float  g_act [BB * T2];   // activity * am
__device__ int    g_nvalid[BB];      // valid frame count per batch

// ------------- kernel A: fused prop + act ---------------------------------
// warps [0, BB*T2)        : imv_proposal = alpha[b,t,:] . arange(T1)
// warps [BB*T2, 2*BB*T2)  : activity from consecutive-frame cosine sim
__global__ void propact_kernel(const float* __restrict__ alpha,
                               const float* __restrict__ mels,
                               const int* __restrict__ mel_mask) {
    int warp = (blockIdx.x * blockDim.x + threadIdx.x) >> 5;
    int lane = threadIdx.x & 31;

    if (warp < BB * T2) {
        // ---- prop: fp32 dot within each float4, fp64 cross-group sum ----
        const float4* row = (const float4*)(alpha + (size_t)warp * T1);
        double acc = 0.0;
#pragma unroll
        for (int i = 0; i < 4; i++) {
            int idx = lane + i * 32;          // float4 index within row (0..127)
            float4 v = row[idx];
            float s = (float)(idx * 4);
            float p = v.x * s + v.y * (s + 1.0f) + v.z * (s + 2.0f) + v.w * (s + 3.0f);
            acc += (double)p;
        }
#pragma unroll
        for (int o = 16; o; o >>= 1) acc += __shfl_down_sync(0xffffffffu, acc, o);
        if (lane == 0) g_prop[warp] = acc;
    } else {
        int w2 = warp - BB * T2;
        if (w2 >= BB * T2) return;
        int t = w2 & (T2 - 1);
        float am = (mel_mask[w2] != 0) ? 1.0f : 0.0f;
        if (t == 0) { if (lane == 0) g_act[w2] = am; return; }
        const float4* r0 = (const float4*)(mels + (size_t)(w2 - 1) * FD);
        const float4* r1 = (const float4*)(mels + (size_t)w2 * FD);
        float4 a = r0[lane], b = r1[lane];
        float dot = a.x * b.x + a.y * b.y + a.z * b.z + a.w * b.w;
        float na  = a.x * a.x + a.y * a.y + a.z * a.z + a.w * a.w;
        float nb  = b.x * b.x + b.y * b.y + b.z * b.z + b.w * b.w;
#pragma unroll
        for (int o = 16; o; o >>= 1) {
            dot += __shfl_down_sync(0xffffffffu, dot, o);
            na  += __shfl_down_sync(0xffffffffu, na,  o);
            nb  += __shfl_down_sync(0xffffffffu, nb,  o);
        }
        if (lane == 0) {
            float n0 = fmaxf(sqrtf(na), 1e-12f);
            float n1 = fmaxf(sqrtf(nb), 1e-12f);
            float cs = dot / (n0 * n1);
            float act = 1.0f / (1.0f + expf(-10.0f * (0.9f - cs)));
            g_act[w2] = act * am;
        }
    }
}

// ------------- kernel B: per-batch gated cumsum + rescale -> imv ----------
__global__ void scan_kernel(const int* __restrict__ mel_mask,
                            const int* __restrict__ text_mask,
                            float* __restrict__ imv_out) {
    int b = blockIdx.x;
    int tid = threadIdx.x;                 // 256 threads, 8 elems each
    __shared__ float s_cum[T2];
    __shared__ float s_part[256];
    __shared__ int   s_red[256];
    __shared__ float s_scale;

    float vals[8];
    float run = 0.0f;
    int nv_local = 0;
#pragma unroll
    for (int i = 0; i < 8; i++) {
        int t = tid * 8 + i;
        int gi = b * T2 + t;
        float eff = 0.0f;
        if (t > 0) {
            double d = g_prop[gi] - g_prop[gi - 1];
            float e = (float)d * g_act[gi];
            eff = fminf(fmaxf(e, 0.0f), 1.0f);
        }
        run += eff;
        vals[i] = run;
        nv_local += (mel_mask[gi] != 0);
    }
    s_part[tid] = run;
    s_red[tid]  = nv_local;
    __syncthreads();
    for (int off = 1; off < 256; off <<= 1) {
        float v = (tid >= off) ? s_part[tid - off] : 0.0f;
        __syncthreads();
        s_part[tid] += v;
        __syncthreads();
    }
    float offset = (tid > 0) ? s_part[tid - 1] : 0.0f;
#pragma unroll
    for (int i = 0; i < 8; i++) s_cum[tid * 8 + i] = vals[i] + offset;

    for (int off = 128; off; off >>= 1) {
        __syncthreads();
        if (tid < off) s_red[tid] += s_red[tid + off];
    }
    __syncthreads();
    int nvalid = s_red[0];
    __syncthreads();
    int tl = (text_mask[b * T1 + tid] != 0) + (text_mask[b * T1 + 256 + tid] != 0);
    s_red[tid] = tl;
    for (int off = 128; off; off >>= 1) {
        __syncthreads();
        if (tid < off) s_red[tid] += s_red[tid + off];
    }
    __syncthreads();
    if (tid == 0) {
        int text_len = s_red[0];
        int last_idx = max(nvalid - 1, 0);
        float aml = (mel_mask[b * T2 + last_idx] != 0) ? 1.0f : 0.0f;
        float last_val = fmaxf(s_cum[last_idx] * aml, 1e-6f);
        float scale = fmaxf((float)text_len - 1.0f, 0.0f) / last_val;
        s_scale = scale;
        g_nvalid[b] = nvalid;
    }
    __syncthreads();
    float scale = s_scale;
#pragma unroll
    for (int i = 0; i < 8; i++) {
        int t = tid * 8 + i;
        int gi = b * T2 + t;
        float am = (mel_mask[gi] != 0) ? 1.0f : 0.0f;
        imv_out[gi] = s_cum[t] * am * scale;
    }
}

// ------------- kernel C: fused Z + gather aligned_mels + durations --------
// Weight phase: one thread per window frame computes its Z inline (<=7 exps)
// and the normalized weight into shared. Accumulate phase: 128 F-threads,
// inner loop unrolled x4 for load-level parallelism.
__global__ void align_kernel(const float* __restrict__ mels,
                             const int* __restrict__ mel_mask,
                             const int* __restrict__ text_mask,
                             const float* __restrict__ imv,
                             float* __restrict__ aligned,
                             float* __restrict__ durations) {
    int s = blockIdx.x;
    int b = blockIdx.y;
    int f = threadIdx.x;                      // 128 threads == FD
    __shared__ int s_range[2];
    __shared__ float s_w[FD];

    int tm = text_mask[b * T1 + s];
    const float* imvb = imv + b * T2;
    if (f == 0) {
        int n = g_nvalid[b];
        float lo = (float)s - WIN, hi = (float)s + WIN;
        int a = 0, c = n;
        while (a < c) { int m = (a + c) >> 1; if (imvb[m] < lo) a = m + 1; else c = m; }
        s_range[0] = a;
        int a2 = a, c2 = n;
        while (a2 < c2) { int m = (a2 + c2) >> 1; if (imvb[m] <= hi) a2 = m + 1; else c2 = m; }
        s_range[1] = a2;
    }
    __syncthreads();

    float acc = 0.0f, D = 0.0f;
    int t0 = s_range[0], t1 = s_range[1];
    if (tm) {
        for (int base = t0; base < t1; base += FD) {
            int nt = min(FD, t1 - base);
            __syncthreads();
            if (f < nt) {
                int gi = b * T2 + base + f;
                float w = 0.0f;
                if (mel_mask[gi]) {
                    float v = imvb[base + f];
                    // inline Z over this frame's own phoneme window
                    int z0 = max(0, (int)ceilf(v - WIN));
                    int z1 = min(T1 - 1, (int)floorf(v + WIN));
                    float Z = 0.0f;
                    for (int sp = z0; sp <= z1; sp++) {
                        if (text_mask[b * T1 + sp]) {
                            float dz = v - (float)sp;
                            Z += expf(-DELTA * dz * dz);
                        }
                    }
                    float d = v - (float)s;
                    float e = expf(-DELTA * d * d);
                    w = (Z > 0.0f) ? (e / Z) : 0.0f;
                }
                s_w[f] = w;
            }
            __syncthreads();
            const float* mb = mels + ((size_t)(b * T2 + base)) * FD + f;
            int j = 0;
            for (; j + 3 < nt; j += 4) {
                float w0 = s_w[j], w1 = s_w[j + 1], w2 = s_w[j + 2], w3 = s_w[j + 3];
                float m0 = mb[(size_t)(j)     * FD];
                float m1 = mb[(size_t)(j + 1) * FD];
                float m2 = mb[(size_t)(j + 2) * FD];
                float m3 = mb[(size_t)(j + 3) * FD];
                acc += w0 * m0; acc += w1 * m1; acc += w2 * m2; acc += w3 * m3;
                D   += (w0 + w1) + (w2 + w3);
            }
            for (; j < nt; j++) {
                float w = s_w[j];
                acc += w * mb[(size_t)j * FD];
                D   += w;
            }
        }
    }
    aligned[((size_t)(b * T1 + s)) * FD + f] = tm ? (acc / (D + EPS)) : 0.0f;
    if (f == 0) durations[b * T1 + s] = tm ? D : 0.0f;
}

// ------------- launch ------------------------------------------------------
extern "C" void kernel_launch(void* const* d_in, const int* in_sizes, int n_in,
                              void* d_out, int out_size) {
    const float* mels      = (const float*)d_in[0];  // [B,T2,F]
    const float* alpha     = (const float*)d_in[1];  // [B,T2,T1]
    const int*   mel_mask  = (const int*)d_in[2];    // [B,T2]
    const int*   text_mask = (const int*)d_in[3];    // [B,T1]

    float* out       = (float*)d_out;
    float* aligned   = out;                              // B*T1*F
    float* durations = out + (size_t)BB * T1 * FD;       // B*T1
    float* imv       = durations + (size_t)BB * T1;      // B*T2

    int nwarp = 2 * BB * T2;                             // prop + act warps
    int nblk  = (nwarp * 32 + 255) / 256;

    propact_kernel<<<nblk, 256>>>(alpha, mels, mel_mask);
    scan_kernel<<<BB, 256>>>(mel_mask, text_mask, imv);
    dim3 grid(T1, BB);
    align_kernel<<<grid, FD>>>(mels, mel_mask, text_mask, imv, aligned, durations);
}

// round 6
// speedup vs baseline: 6.0567x; 1.3489x over previous
#include <cuda_runtime.h>
#include <math.h>

#define BB 16
#define T2 2048
#define T1 512
#define FD 128
#define WIN 3.0f
#define DELTA 10.0f
#define EPS 1e-8f

// ------------- scratch (device globals; no runtime allocation) -------------
__device__ long long g_prop[BB * T2]; // imv_proposal, fixed-point 2^32
__device__ float  g_act [BB * T2];    // activity * am
__device__ int    g_nvalid[BB];       // valid frame count per batch

// ------------- kernel A: fused prop + act ---------------------------------
// warps [0, BB*T2)        : imv_proposal = alpha[b,t,:] . arange(T1)
//                           fp32 fold within float4, EXACT int64 tree after.
// warps [BB*T2, 2*BB*T2)  : activity from consecutive-frame cosine sim
__global__ void propact_kernel(const float* __restrict__ alpha,
                               const float* __restrict__ mels,
                               const int* __restrict__ mel_mask) {
    int warp = (blockIdx.x * blockDim.x + threadIdx.x) >> 5;
    int lane = threadIdx.x & 31;

    if (warp < BB * T2) {
        const float4* row = (const float4*)(alpha + (size_t)warp * T1);
        long long acc = 0;
#pragma unroll
        for (int i = 0; i < 4; i++) {
            int idx = lane + i * 32;          // float4 index within row (0..127)
            float4 v = row[idx];
            float s = (float)(idx * 4);
            float p = v.x * s + v.y * (s + 1.0f) + v.z * (s + 2.0f) + v.w * (s + 3.0f);
            acc += __float2ll_rn(p * 4294967296.0f);   // exact: p*2^32 integral in fp32
        }
#pragma unroll
        for (int o = 16; o; o >>= 1) acc += __shfl_down_sync(0xffffffffu, acc, o);
        if (lane == 0) g_prop[warp] = acc;
    } else {
        int w2 = warp - BB * T2;
        if (w2 >= BB * T2) return;
        int t = w2 & (T2 - 1);
        float am = (mel_mask[w2] != 0) ? 1.0f : 0.0f;
        if (t == 0) { if (lane == 0) g_act[w2] = am; return; }
        const float4* r0 = (const float4*)(mels + (size_t)(w2 - 1) * FD);
        const float4* r1 = (const float4*)(mels + (size_t)w2 * FD);
        float4 a = r0[lane], b = r1[lane];
        float dot = a.x * b.x + a.y * b.y + a.z * b.z + a.w * b.w;
        float na  = a.x * a.x + a.y * a.y + a.z * a.z + a.w * a.w;
        float nb  = b.x * b.x + b.y * b.y + b.z * b.z + b.w * b.w;
#pragma unroll
        for (int o = 16; o; o >>= 1) {
            dot += __shfl_down_sync(0xffffffffu, dot, o);
            na  += __shfl_down_sync(0xffffffffu, na,  o);
            nb  += __shfl_down_sync(0xffffffffu, nb,  o);
        }
        if (lane == 0) {
            float n0 = fmaxf(sqrtf(na), 1e-12f);
            float n1 = fmaxf(sqrtf(nb), 1e-12f);
            float cs = dot / (n0 * n1);
            float act = 1.0f / (1.0f + expf(-10.0f * (0.9f - cs)));
            g_act[w2] = act * am;
        }
    }
}

// ------------- kernel B: per-batch gated cumsum + rescale -> imv ----------
__global__ void scan_kernel(const int* __restrict__ mel_mask,
                            const int* __restrict__ text_mask,
                            float* __restrict__ imv_out) {
    int b = blockIdx.x;
    int tid = threadIdx.x;                 // 256 threads, 8 elems each
    __shared__ float s_cum[T2];
    __shared__ float s_part[256];
    __shared__ int   s_red[256];
    __shared__ float s_scale;

    float vals[8];
    float run = 0.0f;
    int nv_local = 0;
#pragma unroll
    for (int i = 0; i < 8; i++) {
        int t = tid * 8 + i;
        int gi = b * T2 + t;
        float eff = 0.0f;
        if (t > 0) {
            long long d = g_prop[gi] - g_prop[gi - 1];
            float e = (float)d * 2.3283064365386963e-10f * g_act[gi]; // * 2^-32
            eff = fminf(fmaxf(e, 0.0f), 1.0f);
        }
        run += eff;
        vals[i] = run;
        nv_local += (mel_mask[gi] != 0);
    }
    s_part[tid] = run;
    s_red[tid]  = nv_local;
    __syncthreads();
    for (int off = 1; off < 256; off <<= 1) {
        float v = (tid >= off) ? s_part[tid - off] : 0.0f;
        __syncthreads();
        s_part[tid] += v;
        __syncthreads();
    }
    float offset = (tid > 0) ? s_part[tid - 1] : 0.0f;
#pragma unroll
    for (int i = 0; i < 8; i++) s_cum[tid * 8 + i] = vals[i] + offset;

    for (int off = 128; off; off >>= 1) {
        __syncthreads();
        if (tid < off) s_red[tid] += s_red[tid + off];
    }
    __syncthreads();
    int nvalid = s_red[0];
    __syncthreads();
    int tl = (text_mask[b * T1 + tid] != 0) + (text_mask[b * T1 + 256 + tid] != 0);
    s_red[tid] = tl;
    for (int off = 128; off; off >>= 1) {
        __syncthreads();
        if (tid < off) s_red[tid] += s_red[tid + off];
    }
    __syncthreads();
    if (tid == 0) {
        int text_len = s_red[0];
        int last_idx = max(nvalid - 1, 0);
        float aml = (mel_mask[b * T2 + last_idx] != 0) ? 1.0f : 0.0f;
        float last_val = fmaxf(s_cum[last_idx] * aml, 1e-6f);
        float scale = fmaxf((float)text_len - 1.0f, 0.0f) / last_val;
        s_scale = scale;
        g_nvalid[b] = nvalid;
    }
    __syncthreads();
    float scale = s_scale;
#pragma unroll
    for (int i = 0; i < 8; i++) {
        int t = tid * 8 + i;
        int gi = b * T2 + t;
        float am = (mel_mask[gi] != 0) ? 1.0f : 0.0f;
        imv_out[gi] = s_cum[t] * am * scale;
    }
}

// ------------- kernel C: fused Z + gather aligned_mels + durations --------
__global__ void align_kernel(const float* __restrict__ mels,
                             const int* __restrict__ mel_mask,
                             const int* __restrict__ text_mask,
                             const float* __restrict__ imv,
                             float* __restrict__ aligned,
                             float* __restrict__ durations) {
    int s = blockIdx.x;
    int b = blockIdx.y;
    int f = threadIdx.x;                      // 128 threads == FD
    __shared__ int s_range[2];
    __shared__ float s_w[FD];

    int tm = text_mask[b * T1 + s];
    const float* imvb = imv + b * T2;
    if (f == 0) {
        int n = g_nvalid[b];
        float lo = (float)s - WIN, hi = (float)s + WIN;
        int a = 0, c = n;
        while (a < c) { int m = (a + c) >> 1; if (imvb[m] < lo) a = m + 1; else c = m; }
        s_range[0] = a;
        int a2 = a, c2 = n;
        while (a2 < c2) { int m = (a2 + c2) >> 1; if (imvb[m] <= hi) a2 = m + 1; else c2 = m; }
        s_range[1] = a2;
    }
    __syncthreads();

    float acc = 0.0f, D = 0.0f;
    int t0 = s_range[0], t1 = s_range[1];
    if (tm) {
        for (int base = t0; base < t1; base += FD) {
            int nt = min(FD, t1 - base);
            __syncthreads();
            if (f < nt) {
                int gi = b * T2 + base + f;
                float w = 0.0f;
                if (mel_mask[gi]) {
                    float v = imvb[base + f];
                    // inline Z over this frame's own phoneme window
                    int z0 = max(0, (int)ceilf(v - WIN));
                    int z1 = min(T1 - 1, (int)floorf(v + WIN));
                    float Z = 0.0f;
                    for (int sp = z0; sp <= z1; sp++) {
                        if (text_mask[b * T1 + sp]) {
                            float dz = v - (float)sp;
                            Z += expf(-DELTA * dz * dz);
                        }
                    }
                    float d = v - (float)s;
                    float e = expf(-DELTA * d * d);
                    w = (Z > 0.0f) ? (e / Z) : 0.0f;
                }
                s_w[f] = w;
            }
            __syncthreads();
            const float* mb = mels + ((size_t)(b * T2 + base)) * FD + f;
            int j = 0;
            for (; j + 7 < nt; j += 8) {
                float w0 = s_w[j],     w1 = s_w[j + 1], w2 = s_w[j + 2], w3 = s_w[j + 3];
                float w4 = s_w[j + 4], w5 = s_w[j + 5], w6 = s_w[j + 6], w7 = s_w[j + 7];
                float m0 = mb[(size_t)(j)     * FD];
                float m1 = mb[(size_t)(j + 1) * FD];
                float m2 = mb[(size_t)(j + 2) * FD];
                float m3 = mb[(size_t)(j + 3) * FD];
                float m4 = mb[(size_t)(j + 4) * FD];
                float m5 = mb[(size_t)(j + 5) * FD];
                float m6 = mb[(size_t)(j + 6) * FD];
                float m7 = mb[(size_t)(j + 7) * FD];
                acc += w0 * m0; acc += w1 * m1; acc += w2 * m2; acc += w3 * m3;
                acc += w4 * m4; acc += w5 * m5; acc += w6 * m6; acc += w7 * m7;
                D   += ((w0 + w1) + (w2 + w3)) + ((w4 + w5) + (w6 + w7));
            }
            for (; j < nt; j++) {
                float w = s_w[j];
                acc += w * mb[(size_t)j * FD];
                D   += w;
            }
        }
    }
    aligned[((size_t)(b * T1 + s)) * FD + f] = tm ? (acc / (D + EPS)) : 0.0f;
    if (f == 0) durations[b * T1 + s] = tm ? D : 0.0f;
}

// ------------- launch ------------------------------------------------------
extern "C" void kernel_launch(void* const* d_in, const int* in_sizes, int n_in,
                              void* d_out, int out_size) {
    const float* mels      = (const float*)d_in[0];  // [B,T2,F]
    const float* alpha     = (const float*)d_in[1];  // [B,T2,T1]
    const int*   mel_mask  = (const int*)d_in[2];    // [B,T2]
    const int*   text_mask = (const int*)d_in[3];    // [B,T1]

    float* out       = (float*)d_out;
    float* aligned   = out;                              // B*T1*F
    float* durations = out + (size_t)BB * T1 * FD;       // B*T1
    float* imv       = durations + (size_t)BB * T1;      // B*T2

    int nwarp = 2 * BB * T2;                             // prop + act warps
    int nblk  = (nwarp * 32 + 255) / 256;

    propact_kernel<<<nblk, 256>>>(alpha, mels, mel_mask);
    scan_kernel<<<BB, 256>>>(mel_mask, text_mask, imv);
    dim3 grid(T1, BB);
    align_kernel<<<grid, FD>>>(mels, mel_mask, text_mask, imv, aligned, durations);
}

// round 7
// speedup vs baseline: 6.6000x; 1.0897x over previous
#include <cuda_runtime.h>
#include <math.h>

#define BB 16
#define T2 2048
#define T1 512
#define FD 128
#define WIN 3.0f
#define DELTA 10.0f
#define EPS 1e-8f
#define SG 8          // phonemes per align block
#define TCH 64        // frames per smem tile chunk

// ------------- scratch (device globals; no runtime allocation) -------------
__device__ long long g_prop[BB * T2]; // imv_proposal, fixed-point 2^32
__device__ float  g_act [BB * T2];    // activity * am
__device__ int    g_nvalid[BB];       // valid frame count per batch

// ------------- kernel A: fused prop + act ---------------------------------
__global__ void propact_kernel(const float* __restrict__ alpha,
                               const float* __restrict__ mels,
                               const int* __restrict__ mel_mask) {
    int warp = (blockIdx.x * blockDim.x + threadIdx.x) >> 5;
    int lane = threadIdx.x & 31;

    if (warp < BB * T2) {
        const float4* row = (const float4*)(alpha + (size_t)warp * T1);
        // front-batch all 4 LDG.128 for MLP=4
        float4 v0 = row[lane];
        float4 v1 = row[lane + 32];
        float4 v2 = row[lane + 64];
        float4 v3 = row[lane + 96];
        long long acc = 0;
        {
            float s = (float)(lane * 4);
            float p = v0.x * s + v0.y * (s + 1.0f) + v0.z * (s + 2.0f) + v0.w * (s + 3.0f);
            acc += __float2ll_rn(p * 4294967296.0f);
        }
        {
            float s = (float)((lane + 32) * 4);
            float p = v1.x * s + v1.y * (s + 1.0f) + v1.z * (s + 2.0f) + v1.w * (s + 3.0f);
            acc += __float2ll_rn(p * 4294967296.0f);
        }
        {
            float s = (float)((lane + 64) * 4);
            float p = v2.x * s + v2.y * (s + 1.0f) + v2.z * (s + 2.0f) + v2.w * (s + 3.0f);
            acc += __float2ll_rn(p * 4294967296.0f);
        }
        {
            float s = (float)((lane + 96) * 4);
            float p = v3.x * s + v3.y * (s + 1.0f) + v3.z * (s + 2.0f) + v3.w * (s + 3.0f);
            acc += __float2ll_rn(p * 4294967296.0f);
        }
#pragma unroll
        for (int o = 16; o; o >>= 1) acc += __shfl_down_sync(0xffffffffu, acc, o);
        if (lane == 0) g_prop[warp] = acc;
    } else {
        int w2 = warp - BB * T2;
        if (w2 >= BB * T2) return;
        int t = w2 & (T2 - 1);
        float am = (mel_mask[w2] != 0) ? 1.0f : 0.0f;
        if (t == 0) { if (lane == 0) g_act[w2] = am; return; }
        const float4* r0 = (const float4*)(mels + (size_t)(w2 - 1) * FD);
        const float4* r1 = (const float4*)(mels + (size_t)w2 * FD);
        float4 a = r0[lane], b = r1[lane];
        float dot = a.x * b.x + a.y * b.y + a.z * b.z + a.w * b.w;
        float na  = a.x * a.x + a.y * a.y + a.z * a.z + a.w * a.w;
        float nb  = b.x * b.x + b.y * b.y + b.z * b.z + b.w * b.w;
#pragma unroll
        for (int o = 16; o; o >>= 1) {
            dot += __shfl_down_sync(0xffffffffu, dot, o);
            na  += __shfl_down_sync(0xffffffffu, na,  o);
            nb  += __shfl_down_sync(0xffffffffu, nb,  o);
        }
        if (lane == 0) {
            float n0 = fmaxf(sqrtf(na), 1e-12f);
            float n1 = fmaxf(sqrtf(nb), 1e-12f);
            float cs = dot / (n0 * n1);
            float act = 1.0f / (1.0f + expf(-10.0f * (0.9f - cs)));
            g_act[w2] = act * am;
        }
    }
}

// ------------- kernel B: per-batch gated cumsum + rescale -> imv ----------
__global__ void scan_kernel(const int* __restrict__ mel_mask,
                            const int* __restrict__ text_mask,
                            float* __restrict__ imv_out) {
    int b = blockIdx.x;
    int tid = threadIdx.x;                 // 256 threads, 8 elems each
    __shared__ float s_cum[T2];
    __shared__ float s_part[256];
    __shared__ int   s_red[256];
    __shared__ float s_scale;

    float vals[8];
    float run = 0.0f;
    int nv_local = 0;
#pragma unroll
    for (int i = 0; i < 8; i++) {
        int t = tid * 8 + i;
        int gi = b * T2 + t;
        float eff = 0.0f;
        if (t > 0) {
            long long d = g_prop[gi] - g_prop[gi - 1];
            float e = (float)d * 2.3283064365386963e-10f * g_act[gi]; // * 2^-32
            eff = fminf(fmaxf(e, 0.0f), 1.0f);
        }
        run += eff;
        vals[i] = run;
        nv_local += (mel_mask[gi] != 0);
    }
    s_part[tid] = run;
    s_red[tid]  = nv_local;
    __syncthreads();
    for (int off = 1; off < 256; off <<= 1) {
        float v = (tid >= off) ? s_part[tid - off] : 0.0f;
        __syncthreads();
        s_part[tid] += v;
        __syncthreads();
    }
    float offset = (tid > 0) ? s_part[tid - 1] : 0.0f;
#pragma unroll
    for (int i = 0; i < 8; i++) s_cum[tid * 8 + i] = vals[i] + offset;

    for (int off = 128; off; off >>= 1) {
        __syncthreads();
        if (tid < off) s_red[tid] += s_red[tid + off];
    }
    __syncthreads();
    int nvalid = s_red[0];
    __syncthreads();
    int tl = (text_mask[b * T1 + tid] != 0) + (text_mask[b * T1 + 256 + tid] != 0);
    s_red[tid] = tl;
    for (int off = 128; off; off >>= 1) {
        __syncthreads();
        if (tid < off) s_red[tid] += s_red[tid + off];
    }
    __syncthreads();
    if (tid == 0) {
        int text_len = s_red[0];
        int last_idx = max(nvalid - 1, 0);
        float aml = (mel_mask[b * T2 + last_idx] != 0) ? 1.0f : 0.0f;
        float last_val = fmaxf(s_cum[last_idx] * aml, 1e-6f);
        float scale = fmaxf((float)text_len - 1.0f, 0.0f) / last_val;
        s_scale = scale;
        g_nvalid[b] = nvalid;
    }
    __syncthreads();
    float scale = s_scale;
#pragma unroll
    for (int i = 0; i < 8; i++) {
        int t = tid * 8 + i;
        int gi = b * T2 + t;
        float am = (mel_mask[gi] != 0) ? 1.0f : 0.0f;
        imv_out[gi] = s_cum[t] * am * scale;
    }
}

// ------------- kernel C: grouped align (SG phonemes/block, smem mel tile) -
__global__ void align_kernel(const float* __restrict__ mels,
                             const int* __restrict__ mel_mask,
                             const int* __restrict__ text_mask,
                             const float* __restrict__ imv,
                             float* __restrict__ aligned,
                             float* __restrict__ durations) {
    int sg = blockIdx.x;
    int b  = blockIdx.y;
    int s_base = sg * SG;
    int f = threadIdx.x;                      // 128 threads == FD
    __shared__ float tile[TCH][FD];           // 32 KB mel tile
    __shared__ float s_w[TCH][SG];            // 2 KB weight matrix
    __shared__ float s_D[SG];
    __shared__ int s_range[2];

    const float* imvb = imv + b * T2;
    if (f == 0) {
        int n = g_nvalid[b];
        float lo = (float)s_base - WIN;
        float hi = (float)(s_base + SG - 1) + WIN;
        int a = 0, c = n;
        while (a < c) { int m = (a + c) >> 1; if (imvb[m] < lo) a = m + 1; else c = m; }
        s_range[0] = a;
        int a2 = a, c2 = n;
        while (a2 < c2) { int m = (a2 + c2) >> 1; if (imvb[m] <= hi) a2 = m + 1; else c2 = m; }
        s_range[1] = a2;
    }
    if (f < SG) s_D[f] = 0.0f;
    __syncthreads();

    int t0 = s_range[0], t1 = s_range[1];
    float acc[SG];
#pragma unroll
    for (int si = 0; si < SG; si++) acc[si] = 0.0f;

    for (int base = t0; base < t1; base += TCH) {
        int nt = min(TCH, t1 - base);
        __syncthreads();                       // protect prior chunk's tile/w

        // ---- weight phase: thread f handles frame base+f ----
        if (f < nt) {
            int t = base + f;
            int gi = b * T2 + t;
            float w8[SG];
#pragma unroll
            for (int si = 0; si < SG; si++) w8[si] = 0.0f;
            if (mel_mask[gi]) {
                float v = imvb[t];
                int z0 = max(0, (int)ceilf(v - WIN));
                int z1 = min(T1 - 1, (int)floorf(v + WIN));
                float Z = 0.0f;
                for (int sp = z0; sp <= z1; sp++) {
                    if (text_mask[b * T1 + sp]) {
                        float dz = v - (float)sp;
                        Z += expf(-DELTA * dz * dz);
                    }
                }
                if (Z > 0.0f) {
                    float inv = 1.0f / Z;
#pragma unroll
                    for (int si = 0; si < SG; si++) {
                        float d = v - (float)(s_base + si);
                        w8[si] = expf(-DELTA * d * d) * inv;
                    }
                }
            }
#pragma unroll
            for (int si = 0; si < SG; si++) s_w[f][si] = w8[si];
        }

        // ---- tile load: all 128 threads, column f ----
        const float* mb = mels + ((size_t)(b * T2 + base)) * FD + f;
        for (int j = 0; j < nt; j++)
            tile[j][f] = mb[(size_t)j * FD];
        __syncthreads();

        // ---- D accumulation (one thread per phoneme) ----
        if (f < SG) {
            float d = 0.0f;
            for (int j = 0; j < nt; j++) d += s_w[j][f];
            s_D[f] += d;
        }

        // ---- main accumulation: 8 FMAs per tile element ----
        for (int j = 0; j < nt; j++) {
            float m = tile[j][f];
            float4 wa = *(const float4*)&s_w[j][0];
            float4 wb = *(const float4*)&s_w[j][4];
            acc[0] += wa.x * m; acc[1] += wa.y * m;
            acc[2] += wa.z * m; acc[3] += wa.w * m;
            acc[4] += wb.x * m; acc[5] += wb.y * m;
            acc[6] += wb.z * m; acc[7] += wb.w * m;
        }
    }
    __syncthreads();

#pragma unroll
    for (int si = 0; si < SG; si++) {
        int s = s_base + si;
        int tm = text_mask[b * T1 + s];
        float D = s_D[si];
        aligned[((size_t)(b * T1 + s)) * FD + f] = tm ? (acc[si] / (D + EPS)) : 0.0f;
    }
    if (f < SG) {
        int s = s_base + f;
        durations[b * T1 + s] = text_mask[b * T1 + s] ? s_D[f] : 0.0f;
    }
}

// ------------- launch ------------------------------------------------------
extern "C" void kernel_launch(void* const* d_in, const int* in_sizes, int n_in,
                              void* d_out, int out_size) {
    const float* mels      = (const float*)d_in[0];  // [B,T2,F]
    const float* alpha     = (const float*)d_in[1];  // [B,T2,T1]
    const int*   mel_mask  = (const int*)d_in[2];    // [B,T2]
    const int*   text_mask = (const int*)d_in[3];    // [B,T1]

    float* out       = (float*)d_out;
    float* aligned   = out;                              // B*T1*F
    float* durations = out + (size_t)BB * T1 * FD;       // B*T1
    float* imv       = durations + (size_t)BB * T1;      // B*T2

    int nwarp = 2 * BB * T2;                             // prop + act warps
    int nblk  = (nwarp * 32 + 255) / 256;

    propact_kernel<<<nblk, 256>>>(alpha, mels, mel_mask);
    scan_kernel<<<BB, 256>>>(mel_mask, text_mask, imv);
    dim3 grid(T1 / SG, BB);
    align_kernel<<<grid, FD>>>(mels, mel_mask, text_mask, imv, aligned, durations);
}